// round 15
// baseline (speedup 1.0000x reference)
#include <cuda_runtime.h>
#include <cuda_bf16.h>

// VolumeSDFRenderer: R=65536 rays, N=128 samples.
// inputs: distance [R,N] f32, color [R,N,3] f32, depth_values [R,N] f32
// output: concat(out_color [R,3], geometry zeros [R,N,3]) f32.
//
// SINGLE-PHASE, TWO RAYS PER WARP (merge of proven-best R10 + R13 elements):
//  - All distance/depth loaded upfront as float4 (lane k owns samples 4k..4k+3
//    of each ray) — R11/R13's two-phase tail cull is REMOVED: its ~21MB saving
//    was outweighed by the extra serial DRAM trip it added (30.3 -> 31.0us).
//  - One fused dual warp scan (2 independent chains, shuffle cost amortized).
//  - Per-lane color cull: prefix > -ln(T_EPS) -> skip 3 color float4 loads +
//    all math. T_EPS=5e-4 (calibrated: rel_err ~ 0.75*T_EPS -> ~3.7e-4,
//    2.7x under the 1e-3 threshold).
//  - grid 4096 @ 256 threads: measured ~0.9us lower fixed overhead vs 8192.
//  - Both rays' geometry slabs zeroed as one contiguous 192-float4 region.
//  - Plain cache policy (__ldcs/__stcs regressed in R6).
// Exclusive scan = shift-of-inclusive (exact; avoids FAR_DELTA cancellation).

#define ALPHA 10.0f
#define INV_BETA 20.0f      // 1/0.05
#define FAR_DELTA 1e10f
#define CULL_LOG 7.601f     // -ln(5e-4)

__device__ __forceinline__ float sdf_density(float dist) {
    float s = -dist;
    float e = __expf(-INV_BETA * fabsf(s));
    return (s <= 0.0f) ? (0.5f * ALPHA * e) : (ALPHA - 0.5f * ALPHA * e);
}

__global__ __launch_bounds__(256)
void volume_sdf_fused_kernel(const float* __restrict__ distance,
                             const float* __restrict__ color,
                             const float* __restrict__ depth,
                             float* __restrict__ out,
                             int n_rays)
{
    const int warp_id = (blockIdx.x * blockDim.x + threadIdx.x) >> 5;
    const int lane    = threadIdx.x & 31;
    const int ray0 = warp_id * 2;
    if (ray0 >= n_rays) return;
    const int ray1 = ray0 + 1;

    const size_t b0 = (size_t)ray0 * 128;
    const size_t b1 = (size_t)ray1 * 128;

    // ---- front-batched loads: 4 independent float4 LDGs (both rays) ----
    const float4 d0 = reinterpret_cast<const float4*>(distance + b0)[lane];
    const float4 t0 = reinterpret_cast<const float4*>(depth    + b0)[lane];
    const float4 d1 = reinterpret_cast<const float4*>(distance + b1)[lane];
    const float4 t1 = reinterpret_cast<const float4*>(depth    + b1)[lane];

    // ---- zero both rays' geometry: 768 floats = 192 float4, contiguous ----
    {
        float4* geo = reinterpret_cast<float4*>(out + (size_t)n_rays * 3 + (size_t)ray0 * 384);
        const float4 z = make_float4(0.f, 0.f, 0.f, 0.f);
        #pragma unroll
        for (int i = 0; i < 6; i++) geo[lane + i * 32] = z;
    }

    // ---- deltas (need next lane's t.x) ----
    float tn0 = __shfl_down_sync(0xffffffffu, t0.x, 1);
    float tn1 = __shfl_down_sync(0xffffffffu, t1.x, 1);
    float dl03 = (lane == 31) ? FAR_DELTA : (tn0 - t0.w);
    float dl13 = (lane == 31) ? FAR_DELTA : (tn1 - t1.w);

    // ---- d = density * delta, both rays ----
    float a_dd0 = sdf_density(d0.x) * (t0.y - t0.x);
    float a_dd1 = sdf_density(d0.y) * (t0.z - t0.y);
    float a_dd2 = sdf_density(d0.z) * (t0.w - t0.z);
    float a_dd3 = sdf_density(d0.w) * dl03;
    float b_dd0 = sdf_density(d1.x) * (t1.y - t1.x);
    float b_dd1 = sdf_density(d1.y) * (t1.z - t1.y);
    float b_dd2 = sdf_density(d1.z) * (t1.w - t1.z);
    float b_dd3 = sdf_density(d1.w) * dl13;

    // ---- local exclusive prefixes ----
    float a_e1 = a_dd0, a_e2 = a_e1 + a_dd1, a_e3 = a_e2 + a_dd2;
    float b_e1 = b_dd0, b_e2 = b_e1 + b_dd1, b_e3 = b_e2 + b_dd2;

    // ---- fused dual warp inclusive scan (independent chains) ----
    float x0 = a_e3 + a_dd3;
    float x1 = b_e3 + b_dd3;
    #pragma unroll
    for (int off = 1; off < 32; off <<= 1) {
        float y0 = __shfl_up_sync(0xffffffffu, x0, off);
        float y1 = __shfl_up_sync(0xffffffffu, x1, off);
        if (lane >= off) { x0 += y0; x1 += y1; }
    }
    // exclusive = previous lane's inclusive (exact; lane31's FAR_DELTA term
    // never enters any prefix)
    float excl0 = __shfl_up_sync(0xffffffffu, x0, 1);
    float excl1 = __shfl_up_sync(0xffffffffu, x1, 1);
    if (lane == 0) { excl0 = 0.0f; excl1 = 0.0f; }

    float r0 = 0.f, g0 = 0.f, c0 = 0.f;
    float r1 = 0.f, g1 = 0.f, c1 = 0.f;

    // ---- culled color path, ray0 ----
    if (excl0 < CULL_LOG) {
        const float4* cp = reinterpret_cast<const float4*>(color + (size_t)ray0 * 384) + lane * 3;
        const float4 ca = cp[0];
        const float4 cb = cp[1];
        const float4 cc = cp[2];
        float T0 = __expf(-excl0);
        float a0 = __expf(-a_dd0);
        float a1 = __expf(-a_dd1);
        float a2 = __expf(-a_dd2);
        float a3 = __expf(-a_dd3);
        float T1 = T0 * a0, T2 = T1 * a1, T3 = T2 * a2;
        float w0 = (1.0f - a0) * T0;
        float w1 = (1.0f - a1) * T1;
        float w2 = (1.0f - a2) * T2;
        float w3 = (1.0f - a3) * T3;
        r0 = w0 * ca.x + w1 * ca.w + w2 * cb.z + w3 * cc.y;
        g0 = w0 * ca.y + w1 * cb.x + w2 * cb.w + w3 * cc.z;
        c0 = w0 * ca.z + w1 * cb.y + w2 * cc.x + w3 * cc.w;
    }
    // ---- culled color path, ray1 ----
    if (excl1 < CULL_LOG) {
        const float4* cp = reinterpret_cast<const float4*>(color + (size_t)ray1 * 384) + lane * 3;
        const float4 ca = cp[0];
        const float4 cb = cp[1];
        const float4 cc = cp[2];
        float T0 = __expf(-excl1);
        float a0 = __expf(-b_dd0);
        float a1 = __expf(-b_dd1);
        float a2 = __expf(-b_dd2);
        float a3 = __expf(-b_dd3);
        float T1 = T0 * a0, T2 = T1 * a1, T3 = T2 * a2;
        float w0 = (1.0f - a0) * T0;
        float w1 = (1.0f - a1) * T1;
        float w2 = (1.0f - a2) * T2;
        float w3 = (1.0f - a3) * T3;
        r1 = w0 * ca.x + w1 * ca.w + w2 * cb.z + w3 * cc.y;
        g1 = w0 * ca.y + w1 * cb.x + w2 * cb.w + w3 * cc.z;
        c1 = w0 * ca.z + w1 * cb.y + w2 * cc.x + w3 * cc.w;
    }

    // ---- warp reductions (6 independent chains) ----
    #pragma unroll
    for (int off = 16; off >= 1; off >>= 1) {
        r0 += __shfl_xor_sync(0xffffffffu, r0, off);
        g0 += __shfl_xor_sync(0xffffffffu, g0, off);
        c0 += __shfl_xor_sync(0xffffffffu, c0, off);
        r1 += __shfl_xor_sync(0xffffffffu, r1, off);
        g1 += __shfl_xor_sync(0xffffffffu, g1, off);
        c1 += __shfl_xor_sync(0xffffffffu, c1, off);
    }

    if (lane == 0) {
        out[(size_t)ray0 * 3 + 0] = r0;
        out[(size_t)ray0 * 3 + 1] = g0;
        out[(size_t)ray0 * 3 + 2] = c0;
    } else if (lane == 1) {
        out[(size_t)ray1 * 3 + 0] = r1;
        out[(size_t)ray1 * 3 + 1] = g1;
        out[(size_t)ray1 * 3 + 2] = c1;
    }
}

extern "C" void kernel_launch(void* const* d_in, const int* in_sizes, int n_in,
                              void* d_out, int out_size)
{
    const float* distance = (const float*)d_in[0];
    const float* color    = (const float*)d_in[1];
    const float* depth    = (const float*)d_in[2];
    float* out = (float*)d_out;

    const int n_rays = in_sizes[0] / 128;   // R = 65536 (even)

    // two rays per warp; 256 threads = 8 warps = 16 rays per block
    const int rays_per_block = 16;
    const int blocks = (n_rays + rays_per_block - 1) / rays_per_block;
    volume_sdf_fused_kernel<<<blocks, 256>>>(distance, color, depth, out, n_rays);
}